// round 14
// baseline (speedup 1.0000x reference)
#include <cuda_runtime.h>
#include <math.h>

#define N_NODES  50000
#define N_EDGES  800000
#define F_DIM    64
#define L_DIM    1024
#define R_ROUNDS 3
#define N_CLASS  10

#define FB_THREADS 384        // 12 warps = 6 node-groups x 2 bin-groups
#define NPW      8            // nodes per warp
#define NPB      48           // nodes per block

typedef unsigned long long u64;

// Scratch (device globals — no allocation allowed)
__device__ float g_e[N_NODES * F_DIM];   // current embeddings (r after gemm1)
__device__ float g_v[N_NODES * F_DIM];   // v = e + scatter-sum
__device__ float g_f[L_DIM];             // fingerprint accumulator

__device__ __forceinline__ void red_add_v4(float* p, float4 v) {
    asm volatile("red.global.add.v4.f32 [%0], {%1,%2,%3,%4};"
                 :: "l"(p), "f"(v.x), "f"(v.y), "f"(v.z), "f"(v.w) : "memory");
}
__device__ __forceinline__ u64 pack2(float a, float b) {
    u64 r;
    asm("mov.b64 %0, {%1,%2};" : "=l"(r) : "f"(a), "f"(b));
    return r;
}
__device__ __forceinline__ void unpack2(u64 v, float& a, float& b) {
    asm("mov.b64 {%0,%1}, %2;" : "=f"(a), "=f"(b) : "l"(v));
}
__device__ __forceinline__ void fma2(u64& d, u64 a, u64 b) {
    asm("fma.rn.f32x2 %0, %1, %2, %0;" : "+l"(d) : "l"(a), "l"(b));
}

// e = emb[node_feature]; v = e; f = 0
__global__ void gather_init(const int* __restrict__ nf, const float* __restrict__ emb) {
    int tid = blockIdx.x * blockDim.x + threadIdx.x;
    if (tid < L_DIM) g_f[tid] = 0.0f;
    if (tid >= N_NODES * 16) return;
    int node = tid >> 4;
    int c    = tid & 15;
    int ft = nf[node];
    float4 val = ((const float4*)emb)[ft * 16 + c];
    ((float4*)g_e)[node * 16 + c] = val;
    ((float4*)g_v)[node * 16 + c] = val;
}

// v[dst] += e[src] for every edge (vector atomics, 16 threads/edge)
__global__ void scatter_kernel(const int* __restrict__ src, const int* __restrict__ dst) {
    int tid = blockIdx.x * blockDim.x + threadIdx.x;
    if (tid >= N_EDGES * 16) return;
    int e = tid >> 4;
    int c = tid & 15;
    int s = __ldg(src + e);
    int d = __ldg(dst + e);
    float4 val = ((const float4*)g_e)[s * 16 + c];
    red_add_v4(g_v + d * 64 + c * 4, val);
}

// r = relu(v @ Wh[l] + bh[l]); write r into BOTH g_e and g_v (v-init for next round)
__global__ void __launch_bounds__(256) gemm1_kernel(const float* __restrict__ Wh,
                                                    const float* __restrict__ bh, int l) {
    __shared__ __align__(16) float Whs[F_DIM * F_DIM];
    __shared__ __align__(16) float bhs[F_DIM];
    int t = threadIdx.x;
    {
        const float4* W4 = (const float4*)(Wh + l * F_DIM * F_DIM);
        float4* Ws4 = (float4*)Whs;
        for (int i = t; i < F_DIM * F_DIM / 4; i += 256) Ws4[i] = W4[i];
        if (t < F_DIM) bhs[t] = bh[l * F_DIM + t];
    }
    __syncthreads();
    int node = blockIdx.x * 256 + t;
    if (node >= N_NODES) return;

    u64 acc2[32];
#pragma unroll
    for (int j2 = 0; j2 < 32; j2++) acc2[j2] = ((const u64*)bhs)[j2];

    const float4* v4 = ((const float4*)g_v) + node * 16;
    const ulonglong2* W2 = (const ulonglong2*)Whs;
#pragma unroll
    for (int k4 = 0; k4 < 16; k4++) {
        float4 vv = v4[k4];
        float s[4] = {vv.x, vv.y, vv.z, vv.w};
#pragma unroll
        for (int q = 0; q < 4; q++) {
            u64 a = pack2(s[q], s[q]);
            int k = k4 * 4 + q;
#pragma unroll
            for (int j4 = 0; j4 < 16; j4++) {
                ulonglong2 wv = W2[k * 16 + j4];
                fma2(acc2[j4 * 2],     a, wv.x);
                fma2(acc2[j4 * 2 + 1], a, wv.y);
            }
        }
    }
    float4* e4 = ((float4*)g_e) + node * 16;
    float4* w4 = ((float4*)g_v) + node * 16;
#pragma unroll
    for (int j4 = 0; j4 < 16; j4++) {
        float a, b, c, d;
        unpack2(acc2[j4 * 2],     a, b);
        unpack2(acc2[j4 * 2 + 1], c, d);
        float4 o;
        o.x = fmaxf(a, 0.0f); o.y = fmaxf(b, 0.0f);
        o.z = fmaxf(c, 0.0f); o.w = fmaxf(d, 0.0f);
        e4[j4] = o;
        w4[j4] = o;
    }
}

// Fused GEMM2 + softmax + fingerprint accumulation.
// 12 warps = 6 node-groups (wi) x 2 bin-groups (wj).
// Warp (wi,wj): 8 nodes x 512 bins. acc[n*8+g*2+h] = bins wj*512+g*128+lane*4+{2h,2h+1}.
// All FFMA2 operands are loaded as aligned 64-bit pairs:
//   - Wo chunk read as ulonglong2 (LDS.128 -> two u64 halves, no packing MOVs)
//   - r values stored PRE-DUPLICATED (r,r) in smem -> broadcast LDS.64, no MOVs
__global__ void __launch_bounds__(FB_THREADS, 1)
fused_kernel(const float* __restrict__ Wo, const float* __restrict__ bo, int l) {
    __shared__ __align__(16) float Wos[16 * L_DIM];     // 64 KB
    __shared__ __align__(16) u64   rs2[NPB * F_DIM];    // 24 KB (duplicated pairs)
    __shared__ __align__(16) float fpart[L_DIM];        // 4 KB
    __shared__ float pm[NPB][2];                        // partial max
    __shared__ float ps[NPB][2];                        // partial sumexp

    int t = threadIdx.x;
    int w = t >> 5;
    int lane = t & 31;
    int wj = w & 1;        // bin group
    int wi = w >> 1;       // node group
    int nodeBase = blockIdx.x * NPB + wi * NPW;

    for (int i = t; i < L_DIM; i += FB_THREADS) fpart[i] = 0.0f;
    {
        const float4* e4 = (const float4*)g_e;
        for (int i = t; i < NPB * 16; i += FB_THREADS) {
            int node = blockIdx.x * NPB + (i >> 4);
            float4 v = (node < N_NODES) ? e4[node * 16 + (i & 15)]
                                        : make_float4(0.f, 0.f, 0.f, 0.f);
            int base = (i >> 4) * F_DIM + (i & 15) * 4;
            rs2[base + 0] = pack2(v.x, v.x);
            rs2[base + 1] = pack2(v.y, v.y);
            rs2[base + 2] = pack2(v.z, v.z);
            rs2[base + 3] = pack2(v.w, v.w);
        }
    }

    u64 acc[NPW * 8];
    {
        const float4* bo4 = (const float4*)(bo + l * L_DIM);
#pragma unroll
        for (int g = 0; g < 4; g++) {
            float4 b = bo4[wj * 128 + g * 32 + lane];
            u64 b01 = pack2(b.x, b.y);
            u64 b23 = pack2(b.z, b.w);
#pragma unroll
            for (int n = 0; n < NPW; n++) {
                acc[n * 8 + g * 2]     = b01;
                acc[n * 8 + g * 2 + 1] = b23;
            }
        }
    }

    const float4* Wo4 = (const float4*)(Wo + l * F_DIM * L_DIM);
    float4* Wos4 = (float4*)Wos;
    const ulonglong2* Wos2 = (const ulonglong2*)Wos;

    for (int kc = 0; kc < 4; kc++) {
        __syncthreads();
        for (int i = t; i < 4096; i += FB_THREADS) Wos4[i] = Wo4[kc * 4096 + i];
        __syncthreads();
#pragma unroll
        for (int kk = 0; kk < 16; kk++) {
            u64 rk[NPW];
#pragma unroll
            for (int n = 0; n < NPW; n++)
                rk[n] = rs2[(wi * NPW + n) * F_DIM + kc * 16 + kk];
#pragma unroll
            for (int g = 0; g < 4; g++) {
                ulonglong2 wv = Wos2[kk * 256 + wj * 128 + g * 32 + lane];
#pragma unroll
                for (int n = 0; n < NPW; n++) {
                    fma2(acc[n * 8 + g * 2],     rk[n], wv.x);
                    fma2(acc[n * 8 + g * 2 + 1], rk[n], wv.y);
                }
            }
        }
    }

    // Per-warp partial softmax over this warp's 512-bin slice; overwrite acc with exp(x - mj).
#pragma unroll
    for (int n = 0; n < NPW; n++) {
        float mx = -1e30f;
#pragma unroll
        for (int i = 0; i < 8; i++) {
            float a, b; unpack2(acc[n * 8 + i], a, b);
            mx = fmaxf(mx, fmaxf(a, b));
        }
#pragma unroll
        for (int off = 16; off; off >>= 1)
            mx = fmaxf(mx, __shfl_xor_sync(0xffffffffu, mx, off));
        float sum = 0.0f;
#pragma unroll
        for (int i = 0; i < 8; i++) {
            float a, b; unpack2(acc[n * 8 + i], a, b);
            a = __expf(a - mx); b = __expf(b - mx);
            sum += a + b;
            acc[n * 8 + i] = pack2(a, b);
        }
#pragma unroll
        for (int off = 16; off; off >>= 1)
            sum += __shfl_xor_sync(0xffffffffu, sum, off);
        if (lane == 0) {
            pm[wi * NPW + n][wj] = mx;
            ps[wi * NPW + n][wj] = sum;
        }
    }
    __syncthreads();

    // Combine across the two bin-groups and accumulate probabilities.
    u64 pacc[8];
#pragma unroll
    for (int i = 0; i < 8; i++) pacc[i] = 0ull;

#pragma unroll
    for (int n = 0; n < NPW; n++) {
        int nb = wi * NPW + n;
        float m0 = pm[nb][0], m1 = pm[nb][1];
        float m = fmaxf(m0, m1);
        float s = ps[nb][0] * __expf(m0 - m) + ps[nb][1] * __expf(m1 - m);
        float mj = (wj == 0) ? m0 : m1;
        float scale = (nodeBase + n < N_NODES) ? (__expf(mj - m) / s) : 0.0f;
        u64 sc2 = pack2(scale, scale);
#pragma unroll
        for (int i = 0; i < 8; i++) fma2(pacc[i], acc[n * 8 + i], sc2);
    }

#pragma unroll
    for (int i = 0; i < 8; i++) {
        float a, b; unpack2(pacc[i], a, b);
        int g = i >> 1, h = i & 1;
        int base = wj * 512 + g * 128 + lane * 4 + 2 * h;
        atomicAdd(&fpart[base],     a);
        atomicAdd(&fpart[base + 1], b);
    }
    __syncthreads();
    if (t < 256) red_add_v4(g_f + t * 4, ((float4*)fpart)[t]);
}

// out = log_softmax(f @ Wcl + bcl)
__global__ void classify_kernel(const float* __restrict__ Wcl,
                                const float* __restrict__ bcl, float* __restrict__ out) {
    int t = threadIdx.x;
    int lane = t & 31, w = t >> 5;
    float loc[N_CLASS];
#pragma unroll
    for (int c = 0; c < N_CLASS; c++) loc[c] = 0.0f;
    for (int i = t; i < L_DIM; i += 256) {
        float fv = g_f[i];
#pragma unroll
        for (int c = 0; c < N_CLASS; c++) loc[c] += fv * Wcl[i * N_CLASS + c];
    }
#pragma unroll
    for (int c = 0; c < N_CLASS; c++)
#pragma unroll
        for (int off = 16; off; off >>= 1)
            loc[c] += __shfl_xor_sync(0xffffffffu, loc[c], off);

    __shared__ float ws[8][N_CLASS];
    if (lane == 0)
#pragma unroll
        for (int c = 0; c < N_CLASS; c++) ws[w][c] = loc[c];
    __syncthreads();
    if (t == 0) {
        float z[N_CLASS];
#pragma unroll
        for (int c = 0; c < N_CLASS; c++) {
            z[c] = bcl[c];
            for (int k = 0; k < 8; k++) z[c] += ws[k][c];
        }
        float m = z[0];
#pragma unroll
        for (int c = 1; c < N_CLASS; c++) m = fmaxf(m, z[c]);
        float s = 0.0f;
#pragma unroll
        for (int c = 0; c < N_CLASS; c++) s += __expf(z[c] - m);
        float ls = logf(s);
#pragma unroll
        for (int c = 0; c < N_CLASS; c++) out[c] = z[c] - m - ls;
    }
}

extern "C" void kernel_launch(void* const* d_in, const int* in_sizes, int n_in,
                              void* d_out, int out_size) {
    const int*   nf   = (const int*)  d_in[0];
    const int*   esrc = (const int*)  d_in[1];
    const int*   edst = (const int*)  d_in[2];
    const float* emb  = (const float*)d_in[3];
    const float* Wh   = (const float*)d_in[4];
    const float* bh   = (const float*)d_in[5];
    const float* Wo   = (const float*)d_in[6];
    const float* bo   = (const float*)d_in[7];
    const float* Wcl  = (const float*)d_in[8];
    const float* bcl  = (const float*)d_in[9];
    float* out = (float*)d_out;

    gather_init<<<(N_NODES * 16 + 255) / 256, 256>>>(nf, emb);
    for (int l = 0; l < R_ROUNDS; l++) {
        scatter_kernel<<<(N_EDGES * 16 + 255) / 256, 256>>>(esrc, edst);
        gemm1_kernel<<<(N_NODES + 255) / 256, 256>>>(Wh, bh, l);
        fused_kernel<<<(N_NODES + NPB - 1) / NPB, FB_THREADS>>>(Wo, bo, l);
    }
    classify_kernel<<<1, 256>>>(Wcl, bcl, out);
}

// round 15
// speedup vs baseline: 1.2406x; 1.2406x over previous
#include <cuda_runtime.h>
#include <math.h>

#define N_NODES  50000
#define N_EDGES  800000
#define F_DIM    64
#define L_DIM    1024
#define R_ROUNDS 3
#define N_CLASS  10

typedef unsigned int u32;
typedef unsigned long long u64;

// Scratch (device globals — no allocation allowed)
__device__ float g_e[N_NODES * F_DIM];   // current embeddings (r after gemm1)
__device__ float g_v[N_NODES * F_DIM];   // v = e + scatter-sum
__device__ float g_f[L_DIM];             // fingerprint accumulator

__device__ __forceinline__ void red_add_v4(float* p, float4 v) {
    asm volatile("red.global.add.v4.f32 [%0], {%1,%2,%3,%4};"
                 :: "l"(p), "f"(v.x), "f"(v.y), "f"(v.z), "f"(v.w) : "memory");
}
__device__ __forceinline__ void red_add_f32(float* p, float v) {
    asm volatile("red.global.add.f32 [%0], %1;" :: "l"(p), "f"(v) : "memory");
}
__device__ __forceinline__ u64 pack2(float a, float b) {
    u64 r;
    asm("mov.b64 %0, {%1,%2};" : "=l"(r) : "f"(a), "f"(b));
    return r;
}
__device__ __forceinline__ void unpack2(u64 v, float& a, float& b) {
    asm("mov.b64 {%0,%1}, %2;" : "=f"(a), "=f"(b) : "l"(v));
}
__device__ __forceinline__ void fma2(u64& d, u64 a, u64 b) {
    asm("fma.rn.f32x2 %0, %1, %2, %0;" : "+l"(d) : "l"(a), "l"(b));
}
// round fp32 -> tf32 (RNA), returned as fp32 bit pattern with low mantissa zeroed
__device__ __forceinline__ float tf32r(float x) {
    u32 r;
    asm("cvt.rna.tf32.f32 %0, %1;" : "=r"(r) : "f"(x));
    return __uint_as_float(r);
}
__device__ __forceinline__ void mma_tf32(float* c, u32 a0, u32 a1, u32 a2, u32 a3,
                                         u32 b0, u32 b1) {
    asm volatile(
        "mma.sync.aligned.m16n8k8.row.col.f32.tf32.tf32.f32 "
        "{%0,%1,%2,%3}, {%4,%5,%6,%7}, {%8,%9}, {%0,%1,%2,%3};"
        : "+f"(c[0]), "+f"(c[1]), "+f"(c[2]), "+f"(c[3])
        : "r"(a0), "r"(a1), "r"(a2), "r"(a3), "r"(b0), "r"(b1));
}

// e = emb[node_feature]; v = e; f = 0
__global__ void gather_init(const int* __restrict__ nf, const float* __restrict__ emb) {
    int tid = blockIdx.x * blockDim.x + threadIdx.x;
    if (tid < L_DIM) g_f[tid] = 0.0f;
    if (tid >= N_NODES * 16) return;
    int node = tid >> 4;
    int c    = tid & 15;
    int ft = nf[node];
    float4 val = ((const float4*)emb)[ft * 16 + c];
    ((float4*)g_e)[node * 16 + c] = val;
    ((float4*)g_v)[node * 16 + c] = val;
}

// v[dst] += e[src] for every edge (vector atomics, 16 threads/edge)
__global__ void scatter_kernel(const int* __restrict__ src, const int* __restrict__ dst) {
    int tid = blockIdx.x * blockDim.x + threadIdx.x;
    if (tid >= N_EDGES * 16) return;
    int e = tid >> 4;
    int c = tid & 15;
    int s = __ldg(src + e);
    int d = __ldg(dst + e);
    float4 val = ((const float4*)g_e)[s * 16 + c];
    red_add_v4(g_v + d * 64 + c * 4, val);
}

// r = relu(v @ Wh[l] + bh[l]); write r into BOTH g_e and g_v (v-init for next round)
__global__ void __launch_bounds__(256) gemm1_kernel(const float* __restrict__ Wh,
                                                    const float* __restrict__ bh, int l) {
    __shared__ __align__(16) float Whs[F_DIM * F_DIM];
    __shared__ __align__(16) float bhs[F_DIM];
    int t = threadIdx.x;
    {
        const float4* W4 = (const float4*)(Wh + l * F_DIM * F_DIM);
        float4* Ws4 = (float4*)Whs;
        for (int i = t; i < F_DIM * F_DIM / 4; i += 256) Ws4[i] = W4[i];
        if (t < F_DIM) bhs[t] = bh[l * F_DIM + t];
    }
    __syncthreads();
    int node = blockIdx.x * 256 + t;
    if (node >= N_NODES) return;

    u64 acc2[32];
#pragma unroll
    for (int j2 = 0; j2 < 32; j2++) acc2[j2] = ((const u64*)bhs)[j2];

    const float4* v4 = ((const float4*)g_v) + node * 16;
    const ulonglong2* W2 = (const ulonglong2*)Whs;
#pragma unroll
    for (int k4 = 0; k4 < 16; k4++) {
        float4 vv = v4[k4];
        float s[4] = {vv.x, vv.y, vv.z, vv.w};
#pragma unroll
        for (int q = 0; q < 4; q++) {
            u64 a = pack2(s[q], s[q]);
            int k = k4 * 4 + q;
#pragma unroll
            for (int j4 = 0; j4 < 16; j4++) {
                ulonglong2 wv = W2[k * 16 + j4];
                fma2(acc2[j4 * 2],     a, wv.x);
                fma2(acc2[j4 * 2 + 1], a, wv.y);
            }
        }
    }
    float4* e4 = ((float4*)g_e) + node * 16;
    float4* w4 = ((float4*)g_v) + node * 16;
#pragma unroll
    for (int j4 = 0; j4 < 16; j4++) {
        float a, b, c, d;
        unpack2(acc2[j4 * 2],     a, b);
        unpack2(acc2[j4 * 2 + 1], c, d);
        float4 o;
        o.x = fmaxf(a, 0.0f); o.y = fmaxf(b, 0.0f);
        o.z = fmaxf(c, 0.0f); o.w = fmaxf(d, 0.0f);
        e4[j4] = o;
        w4[j4] = o;
    }
}

// ============================================================================
// Fused GEMM2 (tf32 tensor cores, 2-term Wo split) + softmax + fingerprint.
//
// Block: 32 nodes x 1024 bins, 512 threads = 16 warps. Warp nj owns the
// 64-bin slice [nj*64, nj*64+64) for ALL 32 rows -> no cross-warp B reuse
// duplication. mma m16n8k8 tf32: per warp acc[2 m-tiles][8 n-tiles][4].
// Wo streamed in 8-row (one k8 step) chunks; each element split on the fly
// into tf32 hi+lo (stored interleaved float2) -> C = r@Wo_hi + r@Wo_lo is
// exact in Wo; r rounded once to tf32 (node-random error, averages out).
// Bs row stride 1028 float2 => conflict-free b-frag LDS.64.
// ============================================================================
#define BS_STRIDE 1028
__global__ void __launch_bounds__(512, 1)
fused_kernel(const float* __restrict__ Wo, const float* __restrict__ bo, int l) {
    __shared__ __align__(16) float2 Bs[8 * BS_STRIDE];   // 65.8 KB: [krow][bin]={hi,lo}
    __shared__ __align__(16) float  rs[32 * 68];         // 8.7 KB, tf32-rounded r tile
    __shared__ float wm[32][16];                         // per-warp partial max
    __shared__ float ws[32][16];                         // per-warp partial sumexp
    __shared__ float gmax[32];
    __shared__ float gsum[32];

    int t = threadIdx.x;
    int w = t >> 5;               // warp = bin-slice index nj (0..15)
    int lane = t & 31;
    int g = lane >> 2;            // groupID
    int q = lane & 3;             // threadID-in-group
    int nodeBase = blockIdx.x * 32;

    // r tile -> smem, tf32-rounded
    for (int i = t; i < 32 * 64; i += 512) {
        int row = i >> 6, k = i & 63;
        int node = nodeBase + row;
        float v = (node < N_NODES) ? g_e[node * 64 + k] : 0.0f;
        rs[row * 68 + k] = tf32r(v);
    }

    // prefetch Wo chunk 0 (8 rows x 1024 = 2048 float4, 4 per thread)
    const float4* WoG = (const float4*)(Wo + l * F_DIM * L_DIM);
    float4 pf0 = WoG[t], pf1 = WoG[t + 512], pf2 = WoG[t + 1024], pf3 = WoG[t + 1536];

    // acc init from bo (c0/c1 bins adjacent; c2/c3 and mt1 share the same bins)
    float acc[2][8][4];
    {
        const float2* bo2 = (const float2*)(bo + l * L_DIM);
#pragma unroll
        for (int tt = 0; tt < 8; tt++) {
            float2 b = __ldg(bo2 + w * 32 + tt * 4 + q);
            acc[0][tt][0] = b.x; acc[0][tt][1] = b.y;
            acc[0][tt][2] = b.x; acc[0][tt][3] = b.y;
            acc[1][tt][0] = b.x; acc[1][tt][1] = b.y;
            acc[1][tt][2] = b.x; acc[1][tt][3] = b.y;
        }
    }

    // K loop: one 8-row chunk per iteration = one k8 mma step
    for (int c = 0; c < 8; c++) {
        // store prefetched chunk as hi/lo pairs (prev compute already synced)
#pragma unroll
        for (int j = 0; j < 4; j++) {
            float4 v = (j == 0) ? pf0 : (j == 1) ? pf1 : (j == 2) ? pf2 : pf3;
            int p = t + j * 512;                  // float4 index in chunk
            int krow = p >> 8;
            int bin  = (p & 255) * 4;
            float h0 = tf32r(v.x), h1 = tf32r(v.y), h2 = tf32r(v.z), h3 = tf32r(v.w);
            float4* dst = (float4*)(Bs + krow * BS_STRIDE + bin);
            dst[0] = make_float4(h0, tf32r(v.x - h0), h1, tf32r(v.y - h1));
            dst[1] = make_float4(h2, tf32r(v.z - h2), h3, tf32r(v.w - h3));
        }
        __syncthreads();
        if (c < 7) {
            const float4* src = WoG + (c + 1) * 2048;
            pf0 = src[t]; pf1 = src[t + 512]; pf2 = src[t + 1024]; pf3 = src[t + 1536];
        }

        // A fragments for this k8 (rows g,g+8 and g+16,g+24; cols c*8+q, +4)
        int kc = c * 8 + q;
        u32 a0 = __float_as_uint(rs[(g)      * 68 + kc]);
        u32 a1 = __float_as_uint(rs[(g + 8)  * 68 + kc]);
        u32 a2 = __float_as_uint(rs[(g)      * 68 + kc + 4]);
        u32 a3 = __float_as_uint(rs[(g + 8)  * 68 + kc + 4]);
        u32 a4 = __float_as_uint(rs[(g + 16) * 68 + kc]);
        u32 a5 = __float_as_uint(rs[(g + 24) * 68 + kc]);
        u32 a6 = __float_as_uint(rs[(g + 16) * 68 + kc + 4]);
        u32 a7 = __float_as_uint(rs[(g + 24) * 68 + kc + 4]);

#pragma unroll
        for (int tt = 0; tt < 8; tt++) {
            int bin = w * 64 + tt * 8 + g;
            float2 b0 = Bs[q * BS_STRIDE + bin];
            float2 b1 = Bs[(q + 4) * BS_STRIDE + bin];
            u32 b0h = __float_as_uint(b0.x), b0l = __float_as_uint(b0.y);
            u32 b1h = __float_as_uint(b1.x), b1l = __float_as_uint(b1.y);
            mma_tf32(acc[0][tt], a0, a1, a2, a3, b0h, b1h);
            mma_tf32(acc[0][tt], a0, a1, a2, a3, b0l, b1l);
            mma_tf32(acc[1][tt], a4, a5, a6, a7, b0h, b1h);
            mma_tf32(acc[1][tt], a4, a5, a6, a7, b0l, b1l);
        }
        __syncthreads();
    }

    // ---- softmax across warps ----
    // thread's rows (local): R0=g (mt0,c01), R1=g+8 (mt0,c23), R2=g+16, R3=g+24
    float m0 = -1e30f, m1 = -1e30f, m2 = -1e30f, m3 = -1e30f;
#pragma unroll
    for (int tt = 0; tt < 8; tt++) {
        m0 = fmaxf(m0, fmaxf(acc[0][tt][0], acc[0][tt][1]));
        m1 = fmaxf(m1, fmaxf(acc[0][tt][2], acc[0][tt][3]));
        m2 = fmaxf(m2, fmaxf(acc[1][tt][0], acc[1][tt][1]));
        m3 = fmaxf(m3, fmaxf(acc[1][tt][2], acc[1][tt][3]));
    }
#pragma unroll
    for (int off = 1; off <= 2; off <<= 1) {
        m0 = fmaxf(m0, __shfl_xor_sync(0xffffffffu, m0, off));
        m1 = fmaxf(m1, __shfl_xor_sync(0xffffffffu, m1, off));
        m2 = fmaxf(m2, __shfl_xor_sync(0xffffffffu, m2, off));
        m3 = fmaxf(m3, __shfl_xor_sync(0xffffffffu, m3, off));
    }
    if (q == 0) {
        wm[g][w] = m0; wm[g + 8][w] = m1; wm[g + 16][w] = m2; wm[g + 24][w] = m3;
    }
    __syncthreads();
    if (t < 32) {
        float mm = -1e30f;
#pragma unroll
        for (int k = 0; k < 16; k++) mm = fmaxf(mm, wm[t][k]);
        gmax[t] = mm;
    }
    __syncthreads();

    float gm0 = gmax[g], gm1 = gmax[g + 8], gm2 = gmax[g + 16], gm3 = gmax[g + 24];
    float s0 = 0.f, s1 = 0.f, s2 = 0.f, s3 = 0.f;
#pragma unroll
    for (int tt = 0; tt < 8; tt++) {
        acc[0][tt][0] = __expf(acc[0][tt][0] - gm0); s0 += acc[0][tt][0];
        acc[0][tt][1] = __expf(acc[0][tt][1] - gm0); s0 += acc[0][tt][1];
        acc[0][tt][2] = __expf(acc[0][tt][2] - gm1); s1 += acc[0][tt][2];
        acc[0][tt][3] = __expf(acc[0][tt][3] - gm1); s1 += acc[0][tt][3];
        acc[1][tt][0] = __expf(acc[1][tt][0] - gm2); s2 += acc[1][tt][0];
        acc[1][tt][1] = __expf(acc[1][tt][1] - gm2); s2 += acc[1][tt][1];
        acc[1][tt][2] = __expf(acc[1][tt][2] - gm3); s3 += acc[1][tt][2];
        acc[1][tt][3] = __expf(acc[1][tt][3] - gm3); s3 += acc[1][tt][3];
    }
#pragma unroll
    for (int off = 1; off <= 2; off <<= 1) {
        s0 += __shfl_xor_sync(0xffffffffu, s0, off);
        s1 += __shfl_xor_sync(0xffffffffu, s1, off);
        s2 += __shfl_xor_sync(0xffffffffu, s2, off);
        s3 += __shfl_xor_sync(0xffffffffu, s3, off);
    }
    if (q == 0) {
        ws[g][w] = s0; ws[g + 8][w] = s1; ws[g + 16][w] = s2; ws[g + 24][w] = s3;
    }
    __syncthreads();
    if (t < 32) {
        float ss = 0.f;
#pragma unroll
        for (int k = 0; k < 16; k++) ss += ws[t][k];
        gsum[t] = ss;
    }
    __syncthreads();

    float inv0 = (nodeBase + g      < N_NODES) ? 1.0f / gsum[g]      : 0.0f;
    float inv1 = (nodeBase + g + 8  < N_NODES) ? 1.0f / gsum[g + 8]  : 0.0f;
    float inv2 = (nodeBase + g + 16 < N_NODES) ? 1.0f / gsum[g + 16] : 0.0f;
    float inv3 = (nodeBase + g + 24 < N_NODES) ? 1.0f / gsum[g + 24] : 0.0f;

    // accumulate probabilities: sum the 4 rows in-register, reduce across g
    // lanes by shuffle, one RED per bin from lanes g==0.
#pragma unroll
    for (int tt = 0; tt < 8; tt++) {
#pragma unroll
        for (int j = 0; j < 2; j++) {
            float p = acc[0][tt][j] * inv0 + acc[0][tt][j + 2] * inv1
                    + acc[1][tt][j] * inv2 + acc[1][tt][j + 2] * inv3;
            p += __shfl_xor_sync(0xffffffffu, p, 4);
            p += __shfl_xor_sync(0xffffffffu, p, 8);
            p += __shfl_xor_sync(0xffffffffu, p, 16);
            if (g == 0)
                red_add_f32(g_f + w * 64 + tt * 8 + q * 2 + j, p);
        }
    }
}

// out = log_softmax(f @ Wcl + bcl)
__global__ void classify_kernel(const float* __restrict__ Wcl,
                                const float* __restrict__ bcl, float* __restrict__ out) {
    int t = threadIdx.x;
    int lane = t & 31, w = t >> 5;
    float loc[N_CLASS];
#pragma unroll
    for (int c = 0; c < N_CLASS; c++) loc[c] = 0.0f;
    for (int i = t; i < L_DIM; i += 256) {
        float fv = g_f[i];
#pragma unroll
        for (int c = 0; c < N_CLASS; c++) loc[c] += fv * Wcl[i * N_CLASS + c];
    }
#pragma unroll
    for (int c = 0; c < N_CLASS; c++)
#pragma unroll
        for (int off = 16; off; off >>= 1)
            loc[c] += __shfl_xor_sync(0xffffffffu, loc[c], off);

    __shared__ float wsc[8][N_CLASS];
    if (lane == 0)
#pragma unroll
        for (int c = 0; c < N_CLASS; c++) wsc[w][c] = loc[c];
    __syncthreads();
    if (t == 0) {
        float z[N_CLASS];
#pragma unroll
        for (int c = 0; c < N_CLASS; c++) {
            z[c] = bcl[c];
            for (int k = 0; k < 8; k++) z[c] += wsc[k][c];
        }
        float m = z[0];
#pragma unroll
        for (int c = 1; c < N_CLASS; c++) m = fmaxf(m, z[c]);
        float s = 0.0f;
#pragma unroll
        for (int c = 0; c < N_CLASS; c++) s += __expf(z[c] - m);
        float ls = logf(s);
#pragma unroll
        for (int c = 0; c < N_CLASS; c++) out[c] = z[c] - m - ls;
    }
}

extern "C" void kernel_launch(void* const* d_in, const int* in_sizes, int n_in,
                              void* d_out, int out_size) {
    const int*   nf   = (const int*)  d_in[0];
    const int*   esrc = (const int*)  d_in[1];
    const int*   edst = (const int*)  d_in[2];
    const float* emb  = (const float*)d_in[3];
    const float* Wh   = (const float*)d_in[4];
    const float* bh   = (const float*)d_in[5];
    const float* Wo   = (const float*)d_in[6];
    const float* bo   = (const float*)d_in[7];
    const float* Wcl  = (const float*)d_in[8];
    const float* bcl  = (const float*)d_in[9];
    float* out = (float*)d_out;

    gather_init<<<(N_NODES * 16 + 255) / 256, 256>>>(nf, emb);
    for (int l = 0; l < R_ROUNDS; l++) {
        scatter_kernel<<<(N_EDGES * 16 + 255) / 256, 256>>>(esrc, edst);
        gemm1_kernel<<<(N_NODES + 255) / 256, 256>>>(Wh, bh, l);
        fused_kernel<<<(N_NODES + 31) / 32, 512>>>(Wo, bo, l);
    }
    classify_kernel<<<1, 256>>>(Wcl, bcl, out);
}

// round 16
// speedup vs baseline: 1.2435x; 1.0024x over previous
#include <cuda_runtime.h>
#include <math.h>

#define N_NODES  50000
#define N_EDGES  800000
#define F_DIM    64
#define L_DIM    1024
#define R_ROUNDS 3
#define N_CLASS  10

typedef unsigned int u32;
typedef unsigned long long u64;

// Scratch (device globals — no allocation allowed)
__device__ float g_e[N_NODES * F_DIM];   // current embeddings (r after gemm1)
__device__ float g_v[N_NODES * F_DIM];   // v = e + scatter-sum
__device__ float g_f[L_DIM];             // fingerprint accumulator

__device__ __forceinline__ void red_add_v4(float* p, float4 v) {
    asm volatile("red.global.add.v4.f32 [%0], {%1,%2,%3,%4};"
                 :: "l"(p), "f"(v.x), "f"(v.y), "f"(v.z), "f"(v.w) : "memory");
}
__device__ __forceinline__ void red_add_f32(float* p, float v) {
    asm volatile("red.global.add.f32 [%0], %1;" :: "l"(p), "f"(v) : "memory");
}
__device__ __forceinline__ u64 pack2(float a, float b) {
    u64 r;
    asm("mov.b64 %0, {%1,%2};" : "=l"(r) : "f"(a), "f"(b));
    return r;
}
__device__ __forceinline__ void unpack2(u64 v, float& a, float& b) {
    asm("mov.b64 {%0,%1}, %2;" : "=f"(a), "=f"(b) : "l"(v));
}
__device__ __forceinline__ void fma2(u64& d, u64 a, u64 b) {
    asm("fma.rn.f32x2 %0, %1, %2, %0;" : "+l"(d) : "l"(a), "l"(b));
}
// round fp32 -> tf32 (RNA), returned as fp32 bit pattern with low mantissa zeroed
__device__ __forceinline__ float tf32r(float x) {
    u32 r;
    asm("cvt.rna.tf32.f32 %0, %1;" : "=r"(r) : "f"(x));
    return __uint_as_float(r);
}
__device__ __forceinline__ void mma_tf32(float* c, u32 a0, u32 a1, u32 a2, u32 a3,
                                         u32 b0, u32 b1) {
    asm volatile(
        "mma.sync.aligned.m16n8k8.row.col.f32.tf32.tf32.f32 "
        "{%0,%1,%2,%3}, {%4,%5,%6,%7}, {%8,%9}, {%0,%1,%2,%3};"
        : "+f"(c[0]), "+f"(c[1]), "+f"(c[2]), "+f"(c[3])
        : "r"(a0), "r"(a1), "r"(a2), "r"(a3), "r"(b0), "r"(b1));
}

// e = emb[node_feature]; v = e; f = 0
__global__ void gather_init(const int* __restrict__ nf, const float* __restrict__ emb) {
    int tid = blockIdx.x * blockDim.x + threadIdx.x;
    if (tid < L_DIM) g_f[tid] = 0.0f;
    if (tid >= N_NODES * 16) return;
    int node = tid >> 4;
    int c    = tid & 15;
    int ft = nf[node];
    float4 val = ((const float4*)emb)[ft * 16 + c];
    ((float4*)g_e)[node * 16 + c] = val;
    ((float4*)g_v)[node * 16 + c] = val;
}

// v[dst] += e[src] for every edge (vector atomics, 16 threads/edge)
__global__ void scatter_kernel(const int* __restrict__ src, const int* __restrict__ dst) {
    int tid = blockIdx.x * blockDim.x + threadIdx.x;
    if (tid >= N_EDGES * 16) return;
    int e = tid >> 4;
    int c = tid & 15;
    int s = __ldg(src + e);
    int d = __ldg(dst + e);
    float4 val = ((const float4*)g_e)[s * 16 + c];
    red_add_v4(g_v + d * 64 + c * 4, val);
}

// r = relu(v @ Wh[l] + bh[l]); write r into BOTH g_e and g_v (v-init for next round)
__global__ void __launch_bounds__(256) gemm1_kernel(const float* __restrict__ Wh,
                                                    const float* __restrict__ bh, int l) {
    __shared__ __align__(16) float Whs[F_DIM * F_DIM];
    __shared__ __align__(16) float bhs[F_DIM];
    int t = threadIdx.x;
    {
        const float4* W4 = (const float4*)(Wh + l * F_DIM * F_DIM);
        float4* Ws4 = (float4*)Whs;
        for (int i = t; i < F_DIM * F_DIM / 4; i += 256) Ws4[i] = W4[i];
        if (t < F_DIM) bhs[t] = bh[l * F_DIM + t];
    }
    __syncthreads();
    int node = blockIdx.x * 256 + t;
    if (node >= N_NODES) return;

    u64 acc2[32];
#pragma unroll
    for (int j2 = 0; j2 < 32; j2++) acc2[j2] = ((const u64*)bhs)[j2];

    const float4* v4 = ((const float4*)g_v) + node * 16;
    const ulonglong2* W2 = (const ulonglong2*)Whs;
#pragma unroll
    for (int k4 = 0; k4 < 16; k4++) {
        float4 vv = v4[k4];
        float s[4] = {vv.x, vv.y, vv.z, vv.w};
#pragma unroll
        for (int q = 0; q < 4; q++) {
            u64 a = pack2(s[q], s[q]);
            int k = k4 * 4 + q;
#pragma unroll
            for (int j4 = 0; j4 < 16; j4++) {
                ulonglong2 wv = W2[k * 16 + j4];
                fma2(acc2[j4 * 2],     a, wv.x);
                fma2(acc2[j4 * 2 + 1], a, wv.y);
            }
        }
    }
    float4* e4 = ((float4*)g_e) + node * 16;
    float4* w4 = ((float4*)g_v) + node * 16;
#pragma unroll
    for (int j4 = 0; j4 < 16; j4++) {
        float a, b, c, d;
        unpack2(acc2[j4 * 2],     a, b);
        unpack2(acc2[j4 * 2 + 1], c, d);
        float4 o;
        o.x = fmaxf(a, 0.0f); o.y = fmaxf(b, 0.0f);
        o.z = fmaxf(c, 0.0f); o.w = fmaxf(d, 0.0f);
        e4[j4] = o;
        w4[j4] = o;
    }
}

// ============================================================================
// Fused GEMM2 (tf32 tensor cores, 2-term Wo split) + softmax + fingerprint.
//
// Block: 32 nodes x 1024 bins, 512 threads = 16 warps. Warp nj owns the
// 64-bin slice [nj*64, nj*64+64) for ALL 32 rows -> no cross-warp B reuse
// duplication. mma m16n8k8 tf32: per warp acc[2 m-tiles][8 n-tiles][4].
// Wo streamed in 8-row (one k8 step) chunks; each element split on the fly
// into tf32 hi+lo (stored interleaved float2) -> C = r@Wo_hi + r@Wo_lo is
// exact in Wo; r rounded once to tf32 (node-random error, averages out).
// Bs row stride 1028 float2 => conflict-free b-frag LDS.64.
// ============================================================================
#define BS_STRIDE 1028
__global__ void __launch_bounds__(512, 1)
fused_kernel(const float* __restrict__ Wo, const float* __restrict__ bo, int l) {
    __shared__ __align__(16) float2 Bs[8 * BS_STRIDE];   // 65.8 KB: [krow][bin]={hi,lo}
    __shared__ __align__(16) float  rs[32 * 68];         // 8.7 KB, tf32-rounded r tile
    __shared__ float wm[32][16];                         // per-warp partial max
    __shared__ float ws[32][16];                         // per-warp partial sumexp
    __shared__ float gmax[32];
    __shared__ float gsum[32];

    int t = threadIdx.x;
    int w = t >> 5;               // warp = bin-slice index nj (0..15)
    int lane = t & 31;
    int g = lane >> 2;            // groupID
    int q = lane & 3;             // threadID-in-group
    int nodeBase = blockIdx.x * 32;

    // r tile -> smem, tf32-rounded
    for (int i = t; i < 32 * 64; i += 512) {
        int row = i >> 6, k = i & 63;
        int node = nodeBase + row;
        float v = (node < N_NODES) ? g_e[node * 64 + k] : 0.0f;
        rs[row * 68 + k] = tf32r(v);
    }

    // prefetch Wo chunk 0 (8 rows x 1024 = 2048 float4, 4 per thread)
    const float4* WoG = (const float4*)(Wo + l * F_DIM * L_DIM);
    float4 pf0 = WoG[t], pf1 = WoG[t + 512], pf2 = WoG[t + 1024], pf3 = WoG[t + 1536];

    // acc init from bo (c0/c1 bins adjacent; c2/c3 and mt1 share the same bins)
    float acc[2][8][4];
    {
        const float2* bo2 = (const float2*)(bo + l * L_DIM);
#pragma unroll
        for (int tt = 0; tt < 8; tt++) {
            float2 b = __ldg(bo2 + w * 32 + tt * 4 + q);
            acc[0][tt][0] = b.x; acc[0][tt][1] = b.y;
            acc[0][tt][2] = b.x; acc[0][tt][3] = b.y;
            acc[1][tt][0] = b.x; acc[1][tt][1] = b.y;
            acc[1][tt][2] = b.x; acc[1][tt][3] = b.y;
        }
    }

    // K loop: one 8-row chunk per iteration = one k8 mma step
    for (int c = 0; c < 8; c++) {
        // store prefetched chunk as hi/lo pairs (prev compute already synced)
#pragma unroll
        for (int j = 0; j < 4; j++) {
            float4 v = (j == 0) ? pf0 : (j == 1) ? pf1 : (j == 2) ? pf2 : pf3;
            int p = t + j * 512;                  // float4 index in chunk
            int krow = p >> 8;
            int bin  = (p & 255) * 4;
            float h0 = tf32r(v.x), h1 = tf32r(v.y), h2 = tf32r(v.z), h3 = tf32r(v.w);
            float4* dst = (float4*)(Bs + krow * BS_STRIDE + bin);
            dst[0] = make_float4(h0, tf32r(v.x - h0), h1, tf32r(v.y - h1));
            dst[1] = make_float4(h2, tf32r(v.z - h2), h3, tf32r(v.w - h3));
        }
        __syncthreads();
        if (c < 7) {
            const float4* src = WoG + (c + 1) * 2048;
            pf0 = src[t]; pf1 = src[t + 512]; pf2 = src[t + 1024]; pf3 = src[t + 1536];
        }

        // A fragments for this k8 (rows g,g+8 and g+16,g+24; cols c*8+q, +4)
        int kc = c * 8 + q;
        u32 a0 = __float_as_uint(rs[(g)      * 68 + kc]);
        u32 a1 = __float_as_uint(rs[(g + 8)  * 68 + kc]);
        u32 a2 = __float_as_uint(rs[(g)      * 68 + kc + 4]);
        u32 a3 = __float_as_uint(rs[(g + 8)  * 68 + kc + 4]);
        u32 a4 = __float_as_uint(rs[(g + 16) * 68 + kc]);
        u32 a5 = __float_as_uint(rs[(g + 24) * 68 + kc]);
        u32 a6 = __float_as_uint(rs[(g + 16) * 68 + kc + 4]);
        u32 a7 = __float_as_uint(rs[(g + 24) * 68 + kc + 4]);

#pragma unroll
        for (int tt = 0; tt < 8; tt++) {
            int bin = w * 64 + tt * 8 + g;
            float2 b0 = Bs[q * BS_STRIDE + bin];
            float2 b1 = Bs[(q + 4) * BS_STRIDE + bin];
            u32 b0h = __float_as_uint(b0.x), b0l = __float_as_uint(b0.y);
            u32 b1h = __float_as_uint(b1.x), b1l = __float_as_uint(b1.y);
            mma_tf32(acc[0][tt], a0, a1, a2, a3, b0h, b1h);
            mma_tf32(acc[0][tt], a0, a1, a2, a3, b0l, b1l);
            mma_tf32(acc[1][tt], a4, a5, a6, a7, b0h, b1h);
            mma_tf32(acc[1][tt], a4, a5, a6, a7, b0l, b1l);
        }
        __syncthreads();
    }

    // ---- softmax across warps ----
    // thread's rows (local): R0=g (mt0,c01), R1=g+8 (mt0,c23), R2=g+16, R3=g+24
    float m0 = -1e30f, m1 = -1e30f, m2 = -1e30f, m3 = -1e30f;
#pragma unroll
    for (int tt = 0; tt < 8; tt++) {
        m0 = fmaxf(m0, fmaxf(acc[0][tt][0], acc[0][tt][1]));
        m1 = fmaxf(m1, fmaxf(acc[0][tt][2], acc[0][tt][3]));
        m2 = fmaxf(m2, fmaxf(acc[1][tt][0], acc[1][tt][1]));
        m3 = fmaxf(m3, fmaxf(acc[1][tt][2], acc[1][tt][3]));
    }
#pragma unroll
    for (int off = 1; off <= 2; off <<= 1) {
        m0 = fmaxf(m0, __shfl_xor_sync(0xffffffffu, m0, off));
        m1 = fmaxf(m1, __shfl_xor_sync(0xffffffffu, m1, off));
        m2 = fmaxf(m2, __shfl_xor_sync(0xffffffffu, m2, off));
        m3 = fmaxf(m3, __shfl_xor_sync(0xffffffffu, m3, off));
    }
    if (q == 0) {
        wm[g][w] = m0; wm[g + 8][w] = m1; wm[g + 16][w] = m2; wm[g + 24][w] = m3;
    }
    __syncthreads();
    if (t < 32) {
        float mm = -1e30f;
#pragma unroll
        for (int k = 0; k < 16; k++) mm = fmaxf(mm, wm[t][k]);
        gmax[t] = mm;
    }
    __syncthreads();

    float gm0 = gmax[g], gm1 = gmax[g + 8], gm2 = gmax[g + 16], gm3 = gmax[g + 24];
    float s0 = 0.f, s1 = 0.f, s2 = 0.f, s3 = 0.f;
#pragma unroll
    for (int tt = 0; tt < 8; tt++) {
        acc[0][tt][0] = __expf(acc[0][tt][0] - gm0); s0 += acc[0][tt][0];
        acc[0][tt][1] = __expf(acc[0][tt][1] - gm0); s0 += acc[0][tt][1];
        acc[0][tt][2] = __expf(acc[0][tt][2] - gm1); s1 += acc[0][tt][2];
        acc[0][tt][3] = __expf(acc[0][tt][3] - gm1); s1 += acc[0][tt][3];
        acc[1][tt][0] = __expf(acc[1][tt][0] - gm2); s2 += acc[1][tt][0];
        acc[1][tt][1] = __expf(acc[1][tt][1] - gm2); s2 += acc[1][tt][1];
        acc[1][tt][2] = __expf(acc[1][tt][2] - gm3); s3 += acc[1][tt][2];
        acc[1][tt][3] = __expf(acc[1][tt][3] - gm3); s3 += acc[1][tt][3];
    }
#pragma unroll
    for (int off = 1; off <= 2; off <<= 1) {
        s0 += __shfl_xor_sync(0xffffffffu, s0, off);
        s1 += __shfl_xor_sync(0xffffffffu, s1, off);
        s2 += __shfl_xor_sync(0xffffffffu, s2, off);
        s3 += __shfl_xor_sync(0xffffffffu, s3, off);
    }
    if (q == 0) {
        ws[g][w] = s0; ws[g + 8][w] = s1; ws[g + 16][w] = s2; ws[g + 24][w] = s3;
    }
    __syncthreads();
    if (t < 32) {
        float ss = 0.f;
#pragma unroll
        for (int k = 0; k < 16; k++) ss += ws[t][k];
        gsum[t] = ss;
    }
    __syncthreads();

    float inv0 = (nodeBase + g      < N_NODES) ? 1.0f / gsum[g]      : 0.0f;
    float inv1 = (nodeBase + g + 8  < N_NODES) ? 1.0f / gsum[g + 8]  : 0.0f;
    float inv2 = (nodeBase + g + 16 < N_NODES) ? 1.0f / gsum[g + 16] : 0.0f;
    float inv3 = (nodeBase + g + 24 < N_NODES) ? 1.0f / gsum[g + 24] : 0.0f;

    // accumulate probabilities: sum the 4 rows in-register, reduce across g
    // lanes by shuffle, one RED per bin from lanes g==0.
#pragma unroll
    for (int tt = 0; tt < 8; tt++) {
#pragma unroll
        for (int j = 0; j < 2; j++) {
            float p = acc[0][tt][j] * inv0 + acc[0][tt][j + 2] * inv1
                    + acc[1][tt][j] * inv2 + acc[1][tt][j + 2] * inv3;
            p += __shfl_xor_sync(0xffffffffu, p, 4);
            p += __shfl_xor_sync(0xffffffffu, p, 8);
            p += __shfl_xor_sync(0xffffffffu, p, 16);
            if (g == 0)
                red_add_f32(g_f + w * 64 + tt * 8 + q * 2 + j, p);
        }
    }
}

// out = log_softmax(f @ Wcl + bcl)
__global__ void classify_kernel(const float* __restrict__ Wcl,
                                const float* __restrict__ bcl, float* __restrict__ out) {
    int t = threadIdx.x;
    int lane = t & 31, w = t >> 5;
    float loc[N_CLASS];
#pragma unroll
    for (int c = 0; c < N_CLASS; c++) loc[c] = 0.0f;
    for (int i = t; i < L_DIM; i += 256) {
        float fv = g_f[i];
#pragma unroll
        for (int c = 0; c < N_CLASS; c++) loc[c] += fv * Wcl[i * N_CLASS + c];
    }
#pragma unroll
    for (int c = 0; c < N_CLASS; c++)
#pragma unroll
        for (int off = 16; off; off >>= 1)
            loc[c] += __shfl_xor_sync(0xffffffffu, loc[c], off);

    __shared__ float wsc[8][N_CLASS];
    if (lane == 0)
#pragma unroll
        for (int c = 0; c < N_CLASS; c++) wsc[w][c] = loc[c];
    __syncthreads();
    if (t == 0) {
        float z[N_CLASS];
#pragma unroll
        for (int c = 0; c < N_CLASS; c++) {
            z[c] = bcl[c];
            for (int k = 0; k < 8; k++) z[c] += wsc[k][c];
        }
        float m = z[0];
#pragma unroll
        for (int c = 1; c < N_CLASS; c++) m = fmaxf(m, z[c]);
        float s = 0.0f;
#pragma unroll
        for (int c = 0; c < N_CLASS; c++) s += __expf(z[c] - m);
        float ls = logf(s);
#pragma unroll
        for (int c = 0; c < N_CLASS; c++) out[c] = z[c] - m - ls;
    }
}

extern "C" void kernel_launch(void* const* d_in, const int* in_sizes, int n_in,
                              void* d_out, int out_size) {
    const int*   nf   = (const int*)  d_in[0];
    const int*   esrc = (const int*)  d_in[1];
    const int*   edst = (const int*)  d_in[2];
    const float* emb  = (const float*)d_in[3];
    const float* Wh   = (const float*)d_in[4];
    const float* bh   = (const float*)d_in[5];
    const float* Wo   = (const float*)d_in[6];
    const float* bo   = (const float*)d_in[7];
    const float* Wcl  = (const float*)d_in[8];
    const float* bcl  = (const float*)d_in[9];
    float* out = (float*)d_out;

    gather_init<<<(N_NODES * 16 + 255) / 256, 256>>>(nf, emb);
    for (int l = 0; l < R_ROUNDS; l++) {
        scatter_kernel<<<(N_EDGES * 16 + 255) / 256, 256>>>(esrc, edst);
        gemm1_kernel<<<(N_NODES + 255) / 256, 256>>>(Wh, bh, l);
        fused_kernel<<<(N_NODES + 31) / 32, 512>>>(Wo, bo, l);
    }
    classify_kernel<<<1, 256>>>(Wcl, bcl, out);
}

// round 17
// speedup vs baseline: 1.4393x; 1.1575x over previous
#include <cuda_runtime.h>
#include <math.h>

#define N_NODES  50000
#define N_EDGES  800000
#define F_DIM    64
#define L_DIM    1024
#define R_ROUNDS 3
#define N_CLASS  10

typedef unsigned int u32;
typedef unsigned long long u64;

// Scratch (device globals — no allocation allowed)
__device__ float g_e[N_NODES * F_DIM];   // current embeddings (r after gemm1)
__device__ float g_v[N_NODES * F_DIM];   // v = e + scatter-sum
__device__ float g_f[L_DIM];             // fingerprint accumulator
__device__ float g_Wo2[R_ROUNDS * F_DIM * L_DIM * 2];  // pre-split tf32 hi/lo pairs

__device__ __forceinline__ void red_add_v4(float* p, float4 v) {
    asm volatile("red.global.add.v4.f32 [%0], {%1,%2,%3,%4};"
                 :: "l"(p), "f"(v.x), "f"(v.y), "f"(v.z), "f"(v.w) : "memory");
}
__device__ __forceinline__ void red_add_f32(float* p, float v) {
    asm volatile("red.global.add.f32 [%0], %1;" :: "l"(p), "f"(v) : "memory");
}
__device__ __forceinline__ u64 pack2(float a, float b) {
    u64 r;
    asm("mov.b64 %0, {%1,%2};" : "=l"(r) : "f"(a), "f"(b));
    return r;
}
__device__ __forceinline__ void unpack2(u64 v, float& a, float& b) {
    asm("mov.b64 {%0,%1}, %2;" : "=f"(a), "=f"(b) : "l"(v));
}
__device__ __forceinline__ void fma2(u64& d, u64 a, u64 b) {
    asm("fma.rn.f32x2 %0, %1, %2, %0;" : "+l"(d) : "l"(a), "l"(b));
}
__device__ __forceinline__ float tf32r(float x) {
    u32 r;
    asm("cvt.rna.tf32.f32 %0, %1;" : "=r"(r) : "f"(x));
    return __uint_as_float(r);
}
__device__ __forceinline__ void mma_tf32(float* c, u32 a0, u32 a1, u32 a2, u32 a3,
                                         u32 b0, u32 b1) {
    asm volatile(
        "mma.sync.aligned.m16n8k8.row.col.f32.tf32.tf32.f32 "
        "{%0,%1,%2,%3}, {%4,%5,%6,%7}, {%8,%9}, {%0,%1,%2,%3};"
        : "+f"(c[0]), "+f"(c[1]), "+f"(c[2]), "+f"(c[3])
        : "r"(a0), "r"(a1), "r"(a2), "r"(a3), "r"(b0), "r"(b1));
}
__device__ __forceinline__ void cp_async16_s(u32 smem_addr, const void* gsrc) {
    asm volatile("cp.async.cg.shared.global [%0], [%1], 16;"
                 :: "r"(smem_addr), "l"(gsrc) : "memory");
}
#define CP_COMMIT() asm volatile("cp.async.commit_group;" ::: "memory")
#define CP_WAIT1()  asm volatile("cp.async.wait_group 1;" ::: "memory")

// Pre-split Wo into tf32 hi/lo interleaved pairs (all rounds, run once)
__global__ void split_wo(const float* __restrict__ Wo) {
    int i = blockIdx.x * blockDim.x + threadIdx.x;
    if (i >= R_ROUNDS * F_DIM * L_DIM) return;
    float v = Wo[i];
    float h = tf32r(v);
    g_Wo2[i * 2]     = h;
    g_Wo2[i * 2 + 1] = tf32r(v - h);
}

// e = emb[node_feature]; v = e; f = 0
__global__ void gather_init(const int* __restrict__ nf, const float* __restrict__ emb) {
    int tid = blockIdx.x * blockDim.x + threadIdx.x;
    if (tid < L_DIM) g_f[tid] = 0.0f;
    if (tid >= N_NODES * 16) return;
    int node = tid >> 4;
    int c    = tid & 15;
    int ft = nf[node];
    float4 val = ((const float4*)emb)[ft * 16 + c];
    ((float4*)g_e)[node * 16 + c] = val;
    ((float4*)g_v)[node * 16 + c] = val;
}

// v[dst] += e[src] for every edge (vector atomics, 16 threads/edge)
__global__ void scatter_kernel(const int* __restrict__ src, const int* __restrict__ dst) {
    int tid = blockIdx.x * blockDim.x + threadIdx.x;
    if (tid >= N_EDGES * 16) return;
    int e = tid >> 4;
    int c = tid & 15;
    int s = __ldg(src + e);
    int d = __ldg(dst + e);
    float4 val = ((const float4*)g_e)[s * 16 + c];
    red_add_v4(g_v + d * 64 + c * 4, val);
}

// r = relu(v @ Wh[l] + bh[l]); write r into BOTH g_e and g_v (v-init for next round)
__global__ void __launch_bounds__(256) gemm1_kernel(const float* __restrict__ Wh,
                                                    const float* __restrict__ bh, int l) {
    __shared__ __align__(16) float Whs[F_DIM * F_DIM];
    __shared__ __align__(16) float bhs[F_DIM];
    int t = threadIdx.x;
    {
        const float4* W4 = (const float4*)(Wh + l * F_DIM * F_DIM);
        float4* Ws4 = (float4*)Whs;
        for (int i = t; i < F_DIM * F_DIM / 4; i += 256) Ws4[i] = W4[i];
        if (t < F_DIM) bhs[t] = bh[l * F_DIM + t];
    }
    __syncthreads();
    int node = blockIdx.x * 256 + t;
    if (node >= N_NODES) return;

    u64 acc2[32];
#pragma unroll
    for (int j2 = 0; j2 < 32; j2++) acc2[j2] = ((const u64*)bhs)[j2];

    const float4* v4 = ((const float4*)g_v) + node * 16;
    const ulonglong2* W2 = (const ulonglong2*)Whs;
#pragma unroll
    for (int k4 = 0; k4 < 16; k4++) {
        float4 vv = v4[k4];
        float s[4] = {vv.x, vv.y, vv.z, vv.w};
#pragma unroll
        for (int q = 0; q < 4; q++) {
            u64 a = pack2(s[q], s[q]);
            int k = k4 * 4 + q;
#pragma unroll
            for (int j4 = 0; j4 < 16; j4++) {
                ulonglong2 wv = W2[k * 16 + j4];
                fma2(acc2[j4 * 2],     a, wv.x);
                fma2(acc2[j4 * 2 + 1], a, wv.y);
            }
        }
    }
    float4* e4 = ((float4*)g_e) + node * 16;
    float4* w4 = ((float4*)g_v) + node * 16;
#pragma unroll
    for (int j4 = 0; j4 < 16; j4++) {
        float a, b, c, d;
        unpack2(acc2[j4 * 2],     a, b);
        unpack2(acc2[j4 * 2 + 1], c, d);
        float4 o;
        o.x = fmaxf(a, 0.0f); o.y = fmaxf(b, 0.0f);
        o.z = fmaxf(c, 0.0f); o.w = fmaxf(d, 0.0f);
        e4[j4] = o;
        w4[j4] = o;
    }
}

// ============================================================================
// Fused GEMM2 (tf32 mma, PRE-SPLIT hi/lo Wo) + softmax + fingerprint.
// Block: 32 nodes x 1024 bins, 16 warps, warp w owns 64-bin slice for all rows.
// Wo chunks (8 k-rows, hi/lo interleaved) arrive via cp.async into a
// double-buffered Bs; thread t always copies pair-column t of rows j=0..7
// (immediate offsets only). Two syncs/chunk: write-safety + visibility.
// ============================================================================
#define BS_STRIDE 1028
#define BS_BUFBYTES (8 * BS_STRIDE * 8)   // 65792 bytes per buffer
__global__ void __launch_bounds__(512, 1)
fused_kernel(const float* __restrict__ bo, int l) {
    __shared__ __align__(16) float2 Bs[2][8 * BS_STRIDE];  // 2 x 65.8 KB
    __shared__ __align__(16) float  rs[32 * 68];           // tf32-rounded r tile
    __shared__ float wm[32][16];
    __shared__ float ws[32][16];
    __shared__ float gmax[32];
    __shared__ float gsum[32];

    int t = threadIdx.x;
    int w = t >> 5;
    int lane = t & 31;
    int g = lane >> 2;
    int q = lane & 3;
    int nodeBase = blockIdx.x * 32;

    // r tile -> smem, tf32-rounded
    for (int i = t; i < 32 * 64; i += 512) {
        int row = i >> 6, k = i & 63;
        int node = nodeBase + row;
        float v = (node < N_NODES) ? g_e[node * 64 + k] : 0.0f;
        rs[row * 68 + k] = tf32r(v);
    }

    const float4* WoG = (const float4*)(g_Wo2 + (size_t)l * F_DIM * L_DIM * 2);
    u32 dst_base = (u32)__cvta_generic_to_shared(&Bs[0][0]) + t * 16;

    // prologue: chunk 0 -> buffer 0 (thread t = pair-column t, rows j=0..7)
#pragma unroll
    for (int j = 0; j < 8; j++)
        cp_async16_s(dst_base + j * (BS_STRIDE * 8), WoG + j * 512 + t);
    CP_COMMIT();

    // acc init from bo
    float acc[2][8][4];
    {
        const float2* bo2 = (const float2*)(bo + l * L_DIM);
#pragma unroll
        for (int tt = 0; tt < 8; tt++) {
            float2 b = __ldg(bo2 + w * 32 + tt * 4 + q);
            acc[0][tt][0] = b.x; acc[0][tt][1] = b.y;
            acc[0][tt][2] = b.x; acc[0][tt][3] = b.y;
            acc[1][tt][0] = b.x; acc[1][tt][1] = b.y;
            acc[1][tt][2] = b.x; acc[1][tt][3] = b.y;
        }
    }

    for (int c = 0; c < 8; c++) {
        int buf = c & 1;
        __syncthreads();                    // all warps done mma(c-1): buf^1 writable
        if (c < 7) {
            u32 db = dst_base + (buf ^ 1) * BS_BUFBYTES;
            const float4* src = WoG + (c + 1) * 4096 + t;
#pragma unroll
            for (int j = 0; j < 8; j++)
                cp_async16_s(db + j * (BS_STRIDE * 8), src + j * 512);
        }
        CP_COMMIT();
        CP_WAIT1();                         // chunk c landed
        __syncthreads();                    // visible to all warps

        // A fragments for this k8
        int kc = c * 8 + q;
        u32 a0 = __float_as_uint(rs[(g)      * 68 + kc]);
        u32 a1 = __float_as_uint(rs[(g + 8)  * 68 + kc]);
        u32 a2 = __float_as_uint(rs[(g)      * 68 + kc + 4]);
        u32 a3 = __float_as_uint(rs[(g + 8)  * 68 + kc + 4]);
        u32 a4 = __float_as_uint(rs[(g + 16) * 68 + kc]);
        u32 a5 = __float_as_uint(rs[(g + 24) * 68 + kc]);
        u32 a6 = __float_as_uint(rs[(g + 16) * 68 + kc + 4]);
        u32 a7 = __float_as_uint(rs[(g + 24) * 68 + kc + 4]);

        const float2* bq0 = &Bs[buf][q * BS_STRIDE + w * 64 + g];
        const float2* bq1 = bq0 + 4 * BS_STRIDE;
#pragma unroll
        for (int tt = 0; tt < 8; tt++) {
            float2 b0 = bq0[tt * 8];
            float2 b1 = bq1[tt * 8];
            u32 b0h = __float_as_uint(b0.x), b0l = __float_as_uint(b0.y);
            u32 b1h = __float_as_uint(b1.x), b1l = __float_as_uint(b1.y);
            mma_tf32(acc[0][tt], a0, a1, a2, a3, b0h, b1h);
            mma_tf32(acc[0][tt], a0, a1, a2, a3, b0l, b1l);
            mma_tf32(acc[1][tt], a4, a5, a6, a7, b0h, b1h);
            mma_tf32(acc[1][tt], a4, a5, a6, a7, b0l, b1l);
        }
    }

    // ---- softmax across warps ----
    float m0 = -1e30f, m1 = -1e30f, m2 = -1e30f, m3 = -1e30f;
#pragma unroll
    for (int tt = 0; tt < 8; tt++) {
        m0 = fmaxf(m0, fmaxf(acc[0][tt][0], acc[0][tt][1]));
        m1 = fmaxf(m1, fmaxf(acc[0][tt][2], acc[0][tt][3]));
        m2 = fmaxf(m2, fmaxf(acc[1][tt][0], acc[1][tt][1]));
        m3 = fmaxf(m3, fmaxf(acc[1][tt][2], acc[1][tt][3]));
    }
#pragma unroll
    for (int off = 1; off <= 2; off <<= 1) {
        m0 = fmaxf(m0, __shfl_xor_sync(0xffffffffu, m0, off));
        m1 = fmaxf(m1, __shfl_xor_sync(0xffffffffu, m1, off));
        m2 = fmaxf(m2, __shfl_xor_sync(0xffffffffu, m2, off));
        m3 = fmaxf(m3, __shfl_xor_sync(0xffffffffu, m3, off));
    }
    if (q == 0) {
        wm[g][w] = m0; wm[g + 8][w] = m1; wm[g + 16][w] = m2; wm[g + 24][w] = m3;
    }
    __syncthreads();
    if (t < 32) {
        float mm = -1e30f;
#pragma unroll
        for (int k = 0; k < 16; k++) mm = fmaxf(mm, wm[t][k]);
        gmax[t] = mm;
    }
    __syncthreads();

    float gm0 = gmax[g], gm1 = gmax[g + 8], gm2 = gmax[g + 16], gm3 = gmax[g + 24];
    float s0 = 0.f, s1 = 0.f, s2 = 0.f, s3 = 0.f;
#pragma unroll
    for (int tt = 0; tt < 8; tt++) {
        acc[0][tt][0] = __expf(acc[0][tt][0] - gm0); s0 += acc[0][tt][0];
        acc[0][tt][1] = __expf(acc[0][tt][1] - gm0); s0 += acc[0][tt][1];
        acc[0][tt][2] = __expf(acc[0][tt][2] - gm1); s1 += acc[0][tt][2];
        acc[0][tt][3] = __expf(acc[0][tt][3] - gm1); s1 += acc[0][tt][3];
        acc[1][tt][0] = __expf(acc[1][tt][0] - gm2); s2 += acc[1][tt][0];
        acc[1][tt][1] = __expf(acc[1][tt][1] - gm2); s2 += acc[1][tt][1];
        acc[1][tt][2] = __expf(acc[1][tt][2] - gm3); s3 += acc[1][tt][2];
        acc[1][tt][3] = __expf(acc[1][tt][3] - gm3); s3 += acc[1][tt][3];
    }
#pragma unroll
    for (int off = 1; off <= 2; off <<= 1) {
        s0 += __shfl_xor_sync(0xffffffffu, s0, off);
        s1 += __shfl_xor_sync(0xffffffffu, s1, off);
        s2 += __shfl_xor_sync(0xffffffffu, s2, off);
        s3 += __shfl_xor_sync(0xffffffffu, s3, off);
    }
    if (q == 0) {
        ws[g][w] = s0; ws[g + 8][w] = s1; ws[g + 16][w] = s2; ws[g + 24][w] = s3;
    }
    __syncthreads();
    if (t < 32) {
        float ss = 0.f;
#pragma unroll
        for (int k = 0; k < 16; k++) ss += ws[t][k];
        gsum[t] = ss;
    }
    __syncthreads();

    float inv0 = (nodeBase + g      < N_NODES) ? 1.0f / gsum[g]      : 0.0f;
    float inv1 = (nodeBase + g + 8  < N_NODES) ? 1.0f / gsum[g + 8]  : 0.0f;
    float inv2 = (nodeBase + g + 16 < N_NODES) ? 1.0f / gsum[g + 16] : 0.0f;
    float inv3 = (nodeBase + g + 24 < N_NODES) ? 1.0f / gsum[g + 24] : 0.0f;

#pragma unroll
    for (int tt = 0; tt < 8; tt++) {
#pragma unroll
        for (int j = 0; j < 2; j++) {
            float p = acc[0][tt][j] * inv0 + acc[0][tt][j + 2] * inv1
                    + acc[1][tt][j] * inv2 + acc[1][tt][j + 2] * inv3;
            p += __shfl_xor_sync(0xffffffffu, p, 4);
            p += __shfl_xor_sync(0xffffffffu, p, 8);
            p += __shfl_xor_sync(0xffffffffu, p, 16);
            if (g == 0)
                red_add_f32(g_f + w * 64 + tt * 8 + q * 2 + j, p);
        }
    }
}

// out = log_softmax(f @ Wcl + bcl)
__global__ void classify_kernel(const float* __restrict__ Wcl,
                                const float* __restrict__ bcl, float* __restrict__ out) {
    int t = threadIdx.x;
    int lane = t & 31, w = t >> 5;
    float loc[N_CLASS];
#pragma unroll
    for (int c = 0; c < N_CLASS; c++) loc[c] = 0.0f;
    for (int i = t; i < L_DIM; i += 256) {
        float fv = g_f[i];
#pragma unroll
        for (int c = 0; c < N_CLASS; c++) loc[c] += fv * Wcl[i * N_CLASS + c];
    }
#pragma unroll
    for (int c = 0; c < N_CLASS; c++)
#pragma unroll
        for (int off = 16; off; off >>= 1)
            loc[c] += __shfl_xor_sync(0xffffffffu, loc[c], off);

    __shared__ float wsc[8][N_CLASS];
    if (lane == 0)
#pragma unroll
        for (int c = 0; c < N_CLASS; c++) wsc[w][c] = loc[c];
    __syncthreads();
    if (t == 0) {
        float z[N_CLASS];
#pragma unroll
        for (int c = 0; c < N_CLASS; c++) {
            z[c] = bcl[c];
            for (int k = 0; k < 8; k++) z[c] += wsc[k][c];
        }
        float m = z[0];
#pragma unroll
        for (int c = 1; c < N_CLASS; c++) m = fmaxf(m, z[c]);
        float s = 0.0f;
#pragma unroll
        for (int c = 0; c < N_CLASS; c++) s += __expf(z[c] - m);
        float ls = logf(s);
#pragma unroll
        for (int c = 0; c < N_CLASS; c++) out[c] = z[c] - m - ls;
    }
}

extern "C" void kernel_launch(void* const* d_in, const int* in_sizes, int n_in,
                              void* d_out, int out_size) {
    const int*   nf   = (const int*)  d_in[0];
    const int*   esrc = (const int*)  d_in[1];
    const int*   edst = (const int*)  d_in[2];
    const float* emb  = (const float*)d_in[3];
    const float* Wh   = (const float*)d_in[4];
    const float* bh   = (const float*)d_in[5];
    const float* Wo   = (const float*)d_in[6];
    const float* bo   = (const float*)d_in[7];
    const float* Wcl  = (const float*)d_in[8];
    const float* bcl  = (const float*)d_in[9];
    float* out = (float*)d_out;

    split_wo<<<(R_ROUNDS * F_DIM * L_DIM + 255) / 256, 256>>>(Wo);
    gather_init<<<(N_NODES * 16 + 255) / 256, 256>>>(nf, emb);
    for (int l = 0; l < R_ROUNDS; l++) {
        scatter_kernel<<<(N_EDGES * 16 + 255) / 256, 256>>>(esrc, edst);
        gemm1_kernel<<<(N_NODES + 255) / 256, 256>>>(Wh, bh, l);
        fused_kernel<<<(N_NODES + 31) / 32, 512>>>(bo, l);
    }
    classify_kernel<<<1, 256>>>(Wcl, bcl, out);
}